// round 15
// baseline (speedup 1.0000x reference)
#include <cuda_runtime.h>
#include <cuda_fp16.h>
#include <cstdint>

typedef unsigned int u32;

#define Nq 8192
#define Mq 8192
#define Dq 64
#define TNr 128
#define NCHUNK 64

#define SH 36    // fp16 tile row stride in u32
#define ST 68    // fp16 R^T row stride in u32
#define SR 68    // fp32 staging row stride

#define C1F (1.0f/(128.0f*0.69314718055994531f))
#define C2F (2.0f*C1F)

// SMEM u32 offsets
#define OFF_PH   0
#define OFF_RH   (OFF_PH + 128*SH)          // 4 buffers x 128 x SH
#define OFF_RT   (OFF_RH + 4*128*SH)        // 4 buffers x 64 x ST
#define OFF_NUM  (OFF_RT + 4*64*ST)
#define OFF_SQP  (OFF_NUM + 128*SR)
#define OFF_SQR  (OFF_SQP + 128)            // 4 x 128
#define OFF_DEN  (OFF_SQR + 512)            // 2 x 128
#define SMEM_F   (OFF_DEN + 256)

__device__ u32   g_Ph[2 * Nq * 32];
__device__ u32   g_Rh[2 * Mq * 32];
__device__ float g_sqp[2 * Nq];
__device__ float g_sqr[2 * Mq];
__device__ u32   g_Rt[2 * 64 * 4096];

__device__ __forceinline__ void mma_f16(float c[4], u32 a0, u32 a1, u32 a2, u32 a3,
                                        u32 b0, u32 b1)
{
    asm volatile(
        "mma.sync.aligned.m16n8k16.row.col.f32.f16.f16.f32 "
        "{%0,%1,%2,%3}, {%4,%5,%6,%7}, {%8,%9}, {%0,%1,%2,%3};"
        : "+f"(c[0]), "+f"(c[1]), "+f"(c[2]), "+f"(c[3])
        : "r"(a0), "r"(a1), "r"(a2), "r"(a3), "r"(b0), "r"(b1));
}
__device__ __forceinline__ void ldsm4(u32& r0, u32& r1, u32& r2, u32& r3, u32 addr){
    asm volatile("ldmatrix.sync.aligned.m8n8.x4.shared.b16 {%0,%1,%2,%3}, [%4];"
        : "=r"(r0), "=r"(r1), "=r"(r2), "=r"(r3) : "r"(addr));
}
__device__ __forceinline__ float ex2(float x){
    float r; asm("ex2.approx.ftz.f32 %0, %1;" : "=f"(r) : "f"(x)); return r;
}
__device__ __forceinline__ float rcpf(float x){
    float r; asm("rcp.approx.ftz.f32 %0, %1;" : "=f"(r) : "f"(x)); return r;
}
__device__ __forceinline__ u32 pkhf(float lo, float hi){
    u32 d; asm("cvt.rn.f16x2.f32 %0, %1, %2;" : "=r"(d) : "f"(hi), "f"(lo));
    return d;
}
__device__ __forceinline__ void cpasync16(u32 dst, const void* src){
    asm volatile("cp.async.cg.shared.global [%0], [%1], 16;" :: "r"(dst), "l"(src));
}

__global__ void prep_kernel(const float* __restrict__ P, const float* __restrict__ R)
{
    int warp = (blockIdx.x * blockDim.x + threadIdx.x) >> 5;
    int lane = threadIdx.x & 31;
    const float* src; u32* dst; float* nrm;
    if (warp < 2 * Nq){
        src = P + (size_t)warp * Dq; dst = g_Ph + (size_t)warp * 32; nrm = g_sqp + warp;
    } else {
        int row = warp - 2 * Nq;
        src = R + (size_t)row * Dq; dst = g_Rh + (size_t)row * 32; nrm = g_sqr + row;
    }
    float2 v = ((const float2*)src)[lane];
    float x = __half2float(__float2half_rn(v.x));
    float y = __half2float(__float2half_rn(v.y));
    dst[lane] = pkhf(x, y);
    float s = x * x + y * y;
    #pragma unroll
    for (int o = 16; o; o >>= 1) s += __shfl_xor_sync(0xffffffffu, s, o);
    if (lane == 0) nrm[0] = s * C1F;
}

__global__ void transpose_kernel(const float* __restrict__ Rsrc)
{
    __shared__ u32 st[64 * 68];
    const int chunk = blockIdx.x;
    const int t = threadIdx.x;
    const float4* src = (const float4*)(Rsrc + (size_t)chunk * 128 * Dq);
    __half* bp = (__half*)st;
    #pragma unroll
    for (int it = 0; it < 8; it++){
        int idx = t + (it << 8);
        int m = idx >> 4, j4 = idx & 15;
        float4 v = src[idx];
        bp[(4*j4 + 0) * 136 + m] = __float2half_rn(v.x);
        bp[(4*j4 + 1) * 136 + m] = __float2half_rn(v.y);
        bp[(4*j4 + 2) * 136 + m] = __float2half_rn(v.z);
        bp[(4*j4 + 3) * 136 + m] = __float2half_rn(v.w);
    }
    __syncthreads();
    u32* dst = g_Rt + (size_t)chunk * 4096;
    #pragma unroll
    for (int it = 0; it < 4; it++){
        int idx = t + (it << 8);
        int j = idx >> 4, s = idx & 15;
        uint4 v = *(const uint4*)&st[j * 68 + s * 4];
        *(uint4*)&dst[j * 64 + s * 4] = v;
    }
}

__device__ __forceinline__ void load_chunk(u32* RhD, u32* RtD, float* sqD,
                                           const u32* rhg, const u32* rtg,
                                           const float* sqg, int t)
{
    #pragma unroll
    for (int it = 0; it < 4; it++){
        int idx = t + (it << 8);
        int r = idx >> 3, q = idx & 7;
        cpasync16((u32)__cvta_generic_to_shared(&RhD[r * SH + q * 4]), rhg + r * 32 + q * 4);
    }
    #pragma unroll
    for (int it = 0; it < 4; it++){
        int idx = t + (it << 8);
        int j = idx >> 4, s2 = idx & 15;
        cpasync16((u32)__cvta_generic_to_shared(&RtD[j * ST + s2 * 4]), rtg + j * 64 + s2 * 4);
    }
    if (t < 32) cpasync16((u32)__cvta_generic_to_shared(&sqD[t * 4]), sqg + t * 4);
}

__global__ void __launch_bounds__(256, 1) ms_kernel(float* __restrict__ out)
{
    extern __shared__ float sm[];
    u32*   Ph   = (u32*)sm + OFF_PH;
    u32*   Rh0  = (u32*)sm + OFF_RH;
    u32*   Rt0  = (u32*)sm + OFF_RT;
    float* numb = sm + OFF_NUM;
    float* sqp  = sm + OFF_SQP;
    float* sqr0 = sm + OFF_SQR;
    float* denp = sm + OFF_DEN;

    const int t = threadIdx.x;
    const int w = t >> 5, l = t & 31;
    const int gid = l >> 2, tig = l & 3;
    const int sel = l >> 3, rlo = l & 7;       // ldmatrix address roles
    const int b = blockIdx.y;
    const int n0 = blockIdx.x * TNr;
    const u32* Phg = g_Ph + ((size_t)b * Nq + n0) * 32;
    const u32* Rhg = g_Rh + (size_t)b * Mq * 32;
    const u32* Rtg = g_Rt + (size_t)b * 64 * 4096;
    const float* sqpg = g_sqp + b * Nq + n0;
    const float* sqrg = g_sqr + b * Mq;

    const int wm = (w & 3) * 32;
    const int half = w >> 2;
    const int wn1 = half * 64;

    // ldmatrix lane-address bases (byte addresses in shared space)
    const u32 PhB  = (u32)__cvta_generic_to_shared(Ph);
    const u32 RhB0 = (u32)__cvta_generic_to_shared(Rh0);
    const u32 RtB0 = (u32)__cvta_generic_to_shared(Rt0);
    // A(mt): matrix sel -> row wm+16mt+rlo+(sel&1)*8, u32col (sel>>1)*4
    u32 aAddr[2];
    #pragma unroll
    for (int mt = 0; mt < 2; mt++)
        aAddr[mt] = PhB + 4u * ((u32)(wm + 16*mt + rlo + ((sel & 1) << 3)) * SH
                                 + ((u32)(sel >> 1) << 2));
    // B1(q,ks): matrix sel -> row wn1+8*(2q+(sel>>1))+rlo, u32col ks*8+(sel&1)*4
    const u32 b1Off = 4u * ((u32)(wn1 + ((sel >> 1) << 3) + rlo) * SH + ((u32)(sel & 1) << 2));
    // B2(jtp,kt): matrix sel -> row 8*(2jtp+(sel>>1))+rlo, u32col (wn1>>1)+kt*8+(sel&1)*4
    const u32 b2Off = 4u * ((u32)(((sel >> 1) << 3) + rlo) * ST + ((u32)(sel & 1) << 2)
                             + (u32)(wn1 >> 1));

    // ---- Prologue: group0 = Ph + sqp + chunk0 ; group1 = chunk1 ----
    {
        #pragma unroll
        for (int it = 0; it < 4; it++){
            int idx = t + (it << 8);
            int r = idx >> 3, q = idx & 7;
            cpasync16((u32)__cvta_generic_to_shared(&Ph[r * SH + q * 4]), Phg + r * 32 + q * 4);
        }
        if (t < 32) cpasync16((u32)__cvta_generic_to_shared(&sqp[t * 4]), sqpg + t * 4);
        load_chunk(Rh0, Rt0, sqr0, Rhg, Rtg, sqrg, t);
        asm volatile("cp.async.commit_group;");
        load_chunk(Rh0 + 128*SH, Rt0 + 64*ST, sqr0 + 128,
                   Rhg + 128*32, Rtg + 4096, sqrg + 128, t);
        asm volatile("cp.async.commit_group;");
    }

    float nacc[2][8][4];
    float denacc[2][4];
    #pragma unroll
    for (int i = 0; i < 2; i++){
        #pragma unroll
        for (int j = 0; j < 8; j++)
            #pragma unroll
            for (int q = 0; q < 4; q++) nacc[i][j][q] = 0.f;
        #pragma unroll
        for (int q = 0; q < 4; q++) denacc[i][q] = 0.f;
    }
    const u32 ONE2 = 0x3C003C00u;
    u32 kp[2][4][4];

    for (int i = 0; i < NCHUNK; i++){
        const int s = i & 3;
        const u32 RhB = RhB0 + 4u * (u32)(s * 128 * SH);
        const float* sqr = sqr0 + s * 128;

        asm volatile("cp.async.wait_group 1;" ::: "memory");
        __syncthreads();

        // ---- GEMM1 (fp16, ldmatrix frags): S = P . R^T ----
        float sa[2][8][4];
        #pragma unroll
        for (int mt = 0; mt < 2; mt++)
            #pragma unroll
            for (int nt = 0; nt < 8; nt++)
                #pragma unroll
                for (int q = 0; q < 4; q++) sa[mt][nt][q] = 0.f;

        #pragma unroll
        for (int ks = 0; ks < 4; ks++){
            u32 a[2][4];
            #pragma unroll
            for (int mt = 0; mt < 2; mt++)
                ldsm4(a[mt][0], a[mt][1], a[mt][2], a[mt][3], aAddr[mt] + (u32)(ks * 32));
            #pragma unroll
            for (int q = 0; q < 4; q++){
                u32 b00, b01, b10, b11;
                ldsm4(b00, b01, b10, b11,
                      RhB + b1Off + 4u * (u32)(q * 16 * SH + ks * 8));
                #pragma unroll
                for (int mt = 0; mt < 2; mt++){
                    mma_f16(sa[mt][2*q],   a[mt][0], a[mt][1], a[mt][2], a[mt][3], b00, b01);
                    mma_f16(sa[mt][2*q+1], a[mt][0], a[mt][1], a[mt][2], a[mt][3], b10, b11);
                }
            }
        }

        // ---- Prefetch chunk i+2 ----
        if (i + 2 < NCHUNK){
            int s2 = (i + 2) & 3;
            load_chunk(Rh0 + s2 * 128 * SH, Rt0 + s2 * 64 * ST, sqr0 + s2 * 128,
                       Rhg + (size_t)(i + 2) * 128 * 32,
                       Rtg + (size_t)(i + 2) * 4096,
                       sqrg + (size_t)(i + 2) * 128, t);
        }
        asm volatile("cp.async.commit_group;");

        // ---- Fused: epilogue(i) [MUFU] + GEMM2(i-1) [tensor, ldmatrix B] ----
        const u32 RtBp = RtB0 + 4u * (u32)(((i + 3) & 3) * 64 * ST);
        u32 kc[2][4][4];
        #pragma unroll
        for (int kt = 0; kt < 4; kt++){
            #pragma unroll
            for (int mt = 0; mt < 2; mt++){
                int r0 = wm + 16*mt + gid;
                float spa0 = sqp[r0];
                float spa1 = sqp[r0 + 8];
                #pragma unroll
                for (int h = 0; h < 2; h++){
                    int nt = 2*kt + h;
                    int c0 = wn1 + 8*nt + 2*tig;
                    float2 q = *(const float2*)&sqr[c0];
                    float e0 = ex2(fmaf(C2F, sa[mt][nt][0], -spa0 - q.x));
                    float e1 = ex2(fmaf(C2F, sa[mt][nt][1], -spa0 - q.y));
                    float e2 = ex2(fmaf(C2F, sa[mt][nt][2], -spa1 - q.x));
                    float e3 = ex2(fmaf(C2F, sa[mt][nt][3], -spa1 - q.y));
                    kc[mt][kt][2*h + 0] = pkhf(e0, e1);
                    kc[mt][kt][2*h + 1] = pkhf(e2, e3);
                }
            }
            if (i > 0){
                #pragma unroll
                for (int jtp = 0; jtp < 4; jtp++){
                    u32 b00, b01, b10, b11;
                    ldsm4(b00, b01, b10, b11,
                          RtBp + b2Off + 4u * (u32)(jtp * 16 * ST + kt * 8));
                    #pragma unroll
                    for (int mt = 0; mt < 2; mt++){
                        mma_f16(nacc[mt][2*jtp],   kp[mt][kt][0], kp[mt][kt][1],
                                kp[mt][kt][2], kp[mt][kt][3], b00, b01);
                        mma_f16(nacc[mt][2*jtp+1], kp[mt][kt][0], kp[mt][kt][1],
                                kp[mt][kt][2], kp[mt][kt][3], b10, b11);
                    }
                }
                #pragma unroll
                for (int mt = 0; mt < 2; mt++)
                    mma_f16(denacc[mt], kp[mt][kt][0], kp[mt][kt][1],
                            kp[mt][kt][2], kp[mt][kt][3], ONE2, ONE2);
            }
        }
        #pragma unroll
        for (int mt = 0; mt < 2; mt++)
            #pragma unroll
            for (int kt = 0; kt < 4; kt++)
                #pragma unroll
                for (int q = 0; q < 4; q++)
                    kp[mt][kt][q] = kc[mt][kt][q];
    }

    // ---- Drain: GEMM2 for the last chunk ----
    {
        const u32 RtBp = RtB0 + 4u * (u32)(((NCHUNK - 1) & 3) * 64 * ST);
        #pragma unroll
        for (int kt = 0; kt < 4; kt++){
            #pragma unroll
            for (int jtp = 0; jtp < 4; jtp++){
                u32 b00, b01, b10, b11;
                ldsm4(b00, b01, b10, b11,
                      RtBp + b2Off + 4u * (u32)(jtp * 16 * ST + kt * 8));
                #pragma unroll
                for (int mt = 0; mt < 2; mt++){
                    mma_f16(nacc[mt][2*jtp],   kp[mt][kt][0], kp[mt][kt][1],
                            kp[mt][kt][2], kp[mt][kt][3], b00, b01);
                    mma_f16(nacc[mt][2*jtp+1], kp[mt][kt][0], kp[mt][kt][1],
                            kp[mt][kt][2], kp[mt][kt][3], b10, b11);
                }
            }
            #pragma unroll
            for (int mt = 0; mt < 2; mt++)
                mma_f16(denacc[mt], kp[mt][kt][0], kp[mt][kt][1],
                        kp[mt][kt][2], kp[mt][kt][3], ONE2, ONE2);
        }
    }

    // ---- Denominator partials ----
    if (tig == 0){
        #pragma unroll
        for (int mt = 0; mt < 2; mt++){
            denp[half * 128 + wm + 16*mt + gid]     = denacc[mt][0];
            denp[half * 128 + wm + 16*mt + 8 + gid] = denacc[mt][2];
        }
    }

    // ---- Combine the two k-half numerator partials in SMEM ----
    __syncthreads();
    if (half == 0){
        #pragma unroll
        for (int mt = 0; mt < 2; mt++){
            int r0 = wm + 16*mt + gid;
            #pragma unroll
            for (int jt = 0; jt < 8; jt++){
                int c0 = 8*jt + 2*tig;
                *(float2*)&numb[r0 * SR + c0]       = make_float2(nacc[mt][jt][0], nacc[mt][jt][1]);
                *(float2*)&numb[(r0 + 8) * SR + c0] = make_float2(nacc[mt][jt][2], nacc[mt][jt][3]);
            }
        }
    }
    __syncthreads();
    if (half == 1){
        #pragma unroll
        for (int mt = 0; mt < 2; mt++){
            int r0 = wm + 16*mt + gid;
            #pragma unroll
            for (int jt = 0; jt < 8; jt++){
                int c0 = 8*jt + 2*tig;
                float2 u0 = *(const float2*)&numb[r0 * SR + c0];
                float2 u1 = *(const float2*)&numb[(r0 + 8) * SR + c0];
                u0.x += nacc[mt][jt][0]; u0.y += nacc[mt][jt][1];
                u1.x += nacc[mt][jt][2]; u1.y += nacc[mt][jt][3];
                *(float2*)&numb[r0 * SR + c0]       = u0;
                *(float2*)&numb[(r0 + 8) * SR + c0] = u1;
            }
        }
    }
    __syncthreads();

    // ---- Coalesced writeback: out = num / den ----
    float4* Ob = (float4*)(out + ((size_t)b * Nq + n0) * Dq);
    #pragma unroll
    for (int it = 0; it < 8; it++){
        int idx = t + (it << 8);
        int r = idx >> 4, c4 = idx & 15;
        float4 v = *(const float4*)&numb[r * SR + c4 * 4];
        float inv = rcpf(denp[r] + denp[128 + r]);
        v.x *= inv; v.y *= inv; v.z *= inv; v.w *= inv;
        Ob[idx] = v;
    }
}

extern "C" void kernel_launch(void* const* d_in, const int* in_sizes, int n_in,
                              void* d_out, int out_size)
{
    const float* points = (const float*)d_in[0];
    const float* refp   = (const float*)d_in[1];
    float* out          = (float*)d_out;

    {
        int warps = 2 * Nq + 2 * Mq;
        prep_kernel<<<warps / 8, 256>>>(points, refp);
    }
    transpose_kernel<<<128, 256>>>(refp);

    const int smem_bytes = SMEM_F * (int)sizeof(float);
    static int attr_set = 0;
    if (!attr_set){
        cudaFuncSetAttribute(ms_kernel,
                             cudaFuncAttributeMaxDynamicSharedMemorySize, smem_bytes);
        attr_set = 1;
    }
    dim3 grid(Nq / TNr, 2);
    ms_kernel<<<grid, 256, smem_bytes>>>(out);
}

// round 16
// speedup vs baseline: 1.3138x; 1.3138x over previous
#include <cuda_runtime.h>
#include <cuda_fp16.h>
#include <cstdint>

typedef unsigned int u32;

#define Nq 8192
#define Mq 8192
#define Dq 64
#define TNr 128
#define MSEG 8
#define NCH 8            // chunks per CTA = 64 / MSEG

#define SH 36    // fp16 tile row stride in u32: conflict-free frag patterns
#define SR 68    // fp32 staging row stride

#define C1F (1.0f/(128.0f*0.69314718055994531f))
#define C2F (2.0f*C1F)

// SMEM u32 offsets
#define OFF_PH   0                          // 128 x SH (fp16 P)
#define OFF_RH   (OFF_PH + 128*SH)          // 4 buffers x 128 x SH (fp16 R)
#define OFF_RT   (OFF_RH + 4*128*SH)        // 4 buffers x 64 x 68 (fp16 R^T)
#define OFF_NUM  (OFF_RT + 4*64*68)         // 128 x SR fp32 num staging
#define OFF_SQP  (OFF_NUM + 128*SR)
#define OFF_SQR  (OFF_SQP + 128)            // 4 x 128
#define OFF_DEN  (OFF_SQR + 512)            // 2 x 128
#define SMEM_F   (OFF_DEN + 256)

__device__ u32   g_Ph[2 * Nq * 32];
__device__ u32   g_Rh[2 * Mq * 32];
__device__ float g_sqp[2 * Nq];
__device__ float g_sqr[2 * Mq];
__device__ u32   g_Rt[2 * 64 * 4096];
__device__ float g_num[2 * Nq * Dq];
__device__ float g_den[2 * Nq];

__device__ __forceinline__ void mma_f16(float c[4], u32 a0, u32 a1, u32 a2, u32 a3,
                                        u32 b0, u32 b1)
{
    asm volatile(
        "mma.sync.aligned.m16n8k16.row.col.f32.f16.f16.f32 "
        "{%0,%1,%2,%3}, {%4,%5,%6,%7}, {%8,%9}, {%0,%1,%2,%3};"
        : "+f"(c[0]), "+f"(c[1]), "+f"(c[2]), "+f"(c[3])
        : "r"(a0), "r"(a1), "r"(a2), "r"(a3), "r"(b0), "r"(b1));
}
__device__ __forceinline__ float ex2(float x){
    float r; asm("ex2.approx.ftz.f32 %0, %1;" : "=f"(r) : "f"(x)); return r;
}
__device__ __forceinline__ float rcpf(float x){
    float r; asm("rcp.approx.ftz.f32 %0, %1;" : "=f"(r) : "f"(x)); return r;
}
__device__ __forceinline__ u32 pkhf(float lo, float hi){
    u32 d; asm("cvt.rn.f16x2.f32 %0, %1, %2;" : "=r"(d) : "f"(hi), "f"(lo));
    return d;
}
__device__ __forceinline__ void cpasync16(u32 dst, const void* src){
    asm volatile("cp.async.cg.shared.global [%0], [%1], 16;" :: "r"(dst), "l"(src));
}

__global__ void zero_kernel()
{
    int idx = blockIdx.x * blockDim.x + threadIdx.x;       // 0..262143
    ((float4*)g_num)[idx] = make_float4(0.f, 0.f, 0.f, 0.f);
    if (idx < 2 * Nq / 4)
        ((float4*)g_den)[idx] = make_float4(0.f, 0.f, 0.f, 0.f);
}

__global__ void prep_kernel(const float* __restrict__ P, const float* __restrict__ R)
{
    int warp = (blockIdx.x * blockDim.x + threadIdx.x) >> 5;
    int lane = threadIdx.x & 31;
    const float* src; u32* dst; float* nrm;
    if (warp < 2 * Nq){
        src = P + (size_t)warp * Dq; dst = g_Ph + (size_t)warp * 32; nrm = g_sqp + warp;
    } else {
        int row = warp - 2 * Nq;
        src = R + (size_t)row * Dq; dst = g_Rh + (size_t)row * 32; nrm = g_sqr + row;
    }
    float2 v = ((const float2*)src)[lane];
    float x = __half2float(__float2half_rn(v.x));
    float y = __half2float(__float2half_rn(v.y));
    dst[lane] = pkhf(x, y);
    float s = x * x + y * y;
    #pragma unroll
    for (int o = 16; o; o >>= 1) s += __shfl_xor_sync(0xffffffffu, s, o);
    if (lane == 0) nrm[0] = s * C1F;
}

__global__ void transpose_kernel(const float* __restrict__ Rsrc)
{
    __shared__ u32 st[64 * 68];
    const int chunk = blockIdx.x;
    const int t = threadIdx.x;
    const float4* src = (const float4*)(Rsrc + (size_t)chunk * 128 * Dq);
    __half* bp = (__half*)st;
    #pragma unroll
    for (int it = 0; it < 8; it++){
        int idx = t + (it << 8);
        int m = idx >> 4, j4 = idx & 15;
        float4 v = src[idx];
        bp[(4*j4 + 0) * 136 + m] = __float2half_rn(v.x);
        bp[(4*j4 + 1) * 136 + m] = __float2half_rn(v.y);
        bp[(4*j4 + 2) * 136 + m] = __float2half_rn(v.z);
        bp[(4*j4 + 3) * 136 + m] = __float2half_rn(v.w);
    }
    __syncthreads();
    u32* dst = g_Rt + (size_t)chunk * 4096;
    #pragma unroll
    for (int it = 0; it < 4; it++){
        int idx = t + (it << 8);
        int j = idx >> 4, s = idx & 15;
        uint4 v = *(const uint4*)&st[j * 68 + s * 4];
        *(uint4*)&dst[j * 64 + s * 4] = v;
    }
}

__device__ __forceinline__ void load_chunk(u32* RhD, u32* RtD, float* sqD,
                                           const u32* rhg, const u32* rtg,
                                           const float* sqg, int t)
{
    #pragma unroll
    for (int it = 0; it < 4; it++){
        int idx = t + (it << 8);
        int r = idx >> 3, q = idx & 7;
        cpasync16((u32)__cvta_generic_to_shared(&RhD[r * SH + q * 4]), rhg + r * 32 + q * 4);
    }
    #pragma unroll
    for (int it = 0; it < 4; it++){
        int idx = t + (it << 8);
        int j = idx >> 4, s2 = idx & 15;
        cpasync16((u32)__cvta_generic_to_shared(&RtD[j * 68 + s2 * 4]), rtg + j * 64 + s2 * 4);
    }
    if (t < 32) cpasync16((u32)__cvta_generic_to_shared(&sqD[t * 4]), sqg + t * 4);
}

__global__ void __launch_bounds__(256, 1) ms_kernel()
{
    extern __shared__ float sm[];
    u32*   Ph   = (u32*)sm + OFF_PH;
    u32*   Rh0  = (u32*)sm + OFF_RH;
    u32*   Rt0  = (u32*)sm + OFF_RT;
    float* numb = sm + OFF_NUM;
    float* sqp  = sm + OFF_SQP;
    float* sqr0 = sm + OFF_SQR;
    float* denp = sm + OFF_DEN;

    const int t = threadIdx.x;
    const int w = t >> 5, l = t & 31;
    const int gid = l >> 2, tig = l & 3;
    const int b = blockIdx.z;
    const int n0 = blockIdx.x * TNr;
    const int i0 = blockIdx.y * NCH;           // first chunk of this CTA's M-segment
    const u32* Phg = g_Ph + ((size_t)b * Nq + n0) * 32;
    const u32* Rhg = g_Rh + (size_t)b * Mq * 32 + (size_t)i0 * 128 * 32;
    const u32* Rtg = g_Rt + (size_t)b * 64 * 4096 + (size_t)i0 * 4096;
    const float* sqpg = g_sqp + b * Nq + n0;
    const float* sqrg = g_sqr + b * Mq + (size_t)i0 * 128;

    const int wm = (w & 3) * 32;
    const int half = w >> 2;
    const int wn1 = half * 64;

    // ---- Prologue: group0 = Ph + sqp + chunk j=0 ; group1 = chunk j=1 ----
    {
        #pragma unroll
        for (int it = 0; it < 4; it++){
            int idx = t + (it << 8);
            int r = idx >> 3, q = idx & 7;
            cpasync16((u32)__cvta_generic_to_shared(&Ph[r * SH + q * 4]), Phg + r * 32 + q * 4);
        }
        if (t < 32) cpasync16((u32)__cvta_generic_to_shared(&sqp[t * 4]), sqpg + t * 4);
        load_chunk(Rh0, Rt0, sqr0, Rhg, Rtg, sqrg, t);
        asm volatile("cp.async.commit_group;");
        load_chunk(Rh0 + 128*SH, Rt0 + 64*68, sqr0 + 128,
                   Rhg + 128*32, Rtg + 4096, sqrg + 128, t);
        asm volatile("cp.async.commit_group;");
    }

    float nacc[2][8][4];
    float denacc[2][4];
    #pragma unroll
    for (int i = 0; i < 2; i++){
        #pragma unroll
        for (int j = 0; j < 8; j++)
            #pragma unroll
            for (int q = 0; q < 4; q++) nacc[i][j][q] = 0.f;
        #pragma unroll
        for (int q = 0; q < 4; q++) denacc[i][q] = 0.f;
    }
    const u32 ONE2 = 0x3C003C00u;
    u32 kp[2][4][4];   // packed K fragment of chunk j-1 (loop-carried)

    for (int j = 0; j < NCH; j++){
        const int s = j & 3;
        const u32* Rh = Rh0 + s * 128 * SH;
        const float* sqr = sqr0 + s * 128;

        asm volatile("cp.async.wait_group 1;" ::: "memory");
        __syncthreads();

        // ---- GEMM1 (fp16): S = P . R^T  (warp tile 32 x 64) ----
        float sa[2][8][4];
        #pragma unroll
        for (int mt = 0; mt < 2; mt++)
            #pragma unroll
            for (int nt = 0; nt < 8; nt++)
                #pragma unroll
                for (int q = 0; q < 4; q++) sa[mt][nt][q] = 0.f;

        #pragma unroll
        for (int ks = 0; ks < 4; ks++){
            u32 a[2][4];
            #pragma unroll
            for (int mt = 0; mt < 2; mt++){
                const u32* pa = &Ph[(wm + 16*mt + gid) * SH + ks*8 + tig];
                a[mt][0] = pa[0];
                a[mt][1] = pa[8*SH];
                a[mt][2] = pa[4];
                a[mt][3] = pa[8*SH + 4];
            }
            #pragma unroll
            for (int nt = 0; nt < 8; nt++){
                const u32* pb = &Rh[(wn1 + 8*nt + gid) * SH + ks*8 + tig];
                u32 b0 = pb[0], b1 = pb[4];
                #pragma unroll
                for (int mt = 0; mt < 2; mt++)
                    mma_f16(sa[mt][nt], a[mt][0], a[mt][1], a[mt][2], a[mt][3], b0, b1);
            }
        }

        // ---- Prefetch chunk j+2 ----
        if (j + 2 < NCH){
            int s2 = (j + 2) & 3;
            load_chunk(Rh0 + s2 * 128 * SH, Rt0 + s2 * 64 * 68, sqr0 + s2 * 128,
                       Rhg + (size_t)(j + 2) * 128 * 32,
                       Rtg + (size_t)(j + 2) * 4096,
                       sqrg + (size_t)(j + 2) * 128, t);
        }
        asm volatile("cp.async.commit_group;");

        // ---- Fused: epilogue(j) [MUFU] interleaved with GEMM2(j-1) [tensor] ----
        const u32* Rtp = Rt0 + ((j + 3) & 3) * (64 * 68);
        u32 kc[2][4][4];
        #pragma unroll
        for (int kt = 0; kt < 4; kt++){
            #pragma unroll
            for (int mt = 0; mt < 2; mt++){
                int r0 = wm + 16*mt + gid;
                float spa0 = sqp[r0];
                float spa1 = sqp[r0 + 8];
                #pragma unroll
                for (int h = 0; h < 2; h++){
                    int nt = 2*kt + h;
                    int c0 = wn1 + 8*nt + 2*tig;
                    float2 q = *(const float2*)&sqr[c0];
                    float e0 = ex2(fmaf(C2F, sa[mt][nt][0], -spa0 - q.x));
                    float e1 = ex2(fmaf(C2F, sa[mt][nt][1], -spa0 - q.y));
                    float e2 = ex2(fmaf(C2F, sa[mt][nt][2], -spa1 - q.x));
                    float e3 = ex2(fmaf(C2F, sa[mt][nt][3], -spa1 - q.y));
                    kc[mt][kt][2*h + 0] = pkhf(e0, e1);
                    kc[mt][kt][2*h + 1] = pkhf(e2, e3);
                }
            }
            if (j > 0){
                const int koff = (wn1 >> 1) + 8*kt + tig;
                #pragma unroll
                for (int jt = 0; jt < 8; jt++){
                    const u32* pb = &Rtp[(8*jt + gid) * 68 + koff];
                    u32 b0 = pb[0], b1 = pb[4];
                    #pragma unroll
                    for (int mt = 0; mt < 2; mt++)
                        mma_f16(nacc[mt][jt], kp[mt][kt][0], kp[mt][kt][1],
                                kp[mt][kt][2], kp[mt][kt][3], b0, b1);
                }
                #pragma unroll
                for (int mt = 0; mt < 2; mt++)
                    mma_f16(denacc[mt], kp[mt][kt][0], kp[mt][kt][1],
                            kp[mt][kt][2], kp[mt][kt][3], ONE2, ONE2);
            }
        }
        #pragma unroll
        for (int mt = 0; mt < 2; mt++)
            #pragma unroll
            for (int kt = 0; kt < 4; kt++)
                #pragma unroll
                for (int q = 0; q < 4; q++)
                    kp[mt][kt][q] = kc[mt][kt][q];
    }

    // ---- Drain: GEMM2 for the last chunk of this segment ----
    {
        const u32* Rtp = Rt0 + ((NCH - 1) & 3) * (64 * 68);
        #pragma unroll
        for (int kt = 0; kt < 4; kt++){
            const int koff = (wn1 >> 1) + 8*kt + tig;
            #pragma unroll
            for (int jt = 0; jt < 8; jt++){
                const u32* pb = &Rtp[(8*jt + gid) * 68 + koff];
                u32 b0 = pb[0], b1 = pb[4];
                #pragma unroll
                for (int mt = 0; mt < 2; mt++)
                    mma_f16(nacc[mt][jt], kp[mt][kt][0], kp[mt][kt][1],
                            kp[mt][kt][2], kp[mt][kt][3], b0, b1);
            }
            #pragma unroll
            for (int mt = 0; mt < 2; mt++)
                mma_f16(denacc[mt], kp[mt][kt][0], kp[mt][kt][1],
                        kp[mt][kt][2], kp[mt][kt][3], ONE2, ONE2);
        }
    }

    // ---- Denominator partials ----
    if (tig == 0){
        #pragma unroll
        for (int mt = 0; mt < 2; mt++){
            denp[half * 128 + wm + 16*mt + gid]     = denacc[mt][0];
            denp[half * 128 + wm + 16*mt + 8 + gid] = denacc[mt][2];
        }
    }

    // ---- Combine the two k-half numerator partials in SMEM ----
    __syncthreads();
    if (half == 0){
        #pragma unroll
        for (int mt = 0; mt < 2; mt++){
            int r0 = wm + 16*mt + gid;
            #pragma unroll
            for (int jt = 0; jt < 8; jt++){
                int c0 = 8*jt + 2*tig;
                *(float2*)&numb[r0 * SR + c0]       = make_float2(nacc[mt][jt][0], nacc[mt][jt][1]);
                *(float2*)&numb[(r0 + 8) * SR + c0] = make_float2(nacc[mt][jt][2], nacc[mt][jt][3]);
            }
        }
    }
    __syncthreads();
    if (half == 1){
        #pragma unroll
        for (int mt = 0; mt < 2; mt++){
            int r0 = wm + 16*mt + gid;
            #pragma unroll
            for (int jt = 0; jt < 8; jt++){
                int c0 = 8*jt + 2*tig;
                float2 u0 = *(const float2*)&numb[r0 * SR + c0];
                float2 u1 = *(const float2*)&numb[(r0 + 8) * SR + c0];
                u0.x += nacc[mt][jt][0]; u0.y += nacc[mt][jt][1];
                u1.x += nacc[mt][jt][2]; u1.y += nacc[mt][jt][3];
                *(float2*)&numb[r0 * SR + c0]       = u0;
                *(float2*)&numb[(r0 + 8) * SR + c0] = u1;
            }
        }
    }
    __syncthreads();

    // ---- Cross-CTA combine: atomicAdd num tile + den into global ----
    float* gnum = g_num + ((size_t)b * Nq + n0) * Dq;
    #pragma unroll
    for (int it = 0; it < 8; it++){
        int idx = t + (it << 8);
        int r = idx >> 4, c4 = idx & 15;
        float4 v = *(const float4*)&numb[r * SR + c4 * 4];
        float* d = gnum + r * Dq + c4 * 4;
        atomicAdd(d + 0, v.x);
        atomicAdd(d + 1, v.y);
        atomicAdd(d + 2, v.z);
        atomicAdd(d + 3, v.w);
    }
    if (t < 128)
        atomicAdd(&g_den[b * Nq + n0 + t], denp[t] + denp[128 + t]);
}

__global__ void divide_kernel(float* __restrict__ out)
{
    int idx = blockIdx.x * blockDim.x + threadIdx.x;   // 0..262143 float4s
    int row = idx >> 4;                                 // 16 float4 per row
    float4 v = ((const float4*)g_num)[idx];
    float inv = rcpf(g_den[row]);
    v.x *= inv; v.y *= inv; v.z *= inv; v.w *= inv;
    ((float4*)out)[idx] = v;
}

extern "C" void kernel_launch(void* const* d_in, const int* in_sizes, int n_in,
                              void* d_out, int out_size)
{
    const float* points = (const float*)d_in[0];
    const float* refp   = (const float*)d_in[1];
    float* out          = (float*)d_out;

    zero_kernel<<<1024, 256>>>();
    {
        int warps = 2 * Nq + 2 * Mq;
        prep_kernel<<<warps / 8, 256>>>(points, refp);
    }
    transpose_kernel<<<128, 256>>>(refp);

    const int smem_bytes = SMEM_F * (int)sizeof(float);
    static int attr_set = 0;
    if (!attr_set){
        cudaFuncSetAttribute(ms_kernel,
                             cudaFuncAttributeMaxDynamicSharedMemorySize, smem_bytes);
        attr_set = 1;
    }
    dim3 grid(Nq / TNr, MSEG, 2);
    ms_kernel<<<grid, 256, smem_bytes>>>();
    divide_kernel<<<1024, 256>>>(out);
}